// round 9
// baseline (speedup 1.0000x reference)
#include <cuda_runtime.h>
#include <cuda_fp16.h>
#include <cstdint>
#include <cstddef>

#define NN 50000
#define NE 800000
#define DI 256
#define DO 256
#define NR 8

#define NBLK ((NN + 255) / 256)   // 196 scan blocks

// fp16 scratch: xt[r][n][o]  (204.8 MB)
__device__ __half g_xt[(size_t)NR * NN * DO];
// fp16 copies of x and W
__device__ __half g_xh[(size_t)NN * DI];      // 25.6 MB
__device__ __half g_wh[(size_t)NR * DI * DO]; // 1 MB
// CSR-by-destination scaffolding
__device__ int g_cnt[NN];
__device__ int g_offs[NN + 1];
__device__ int g_curs[NN];
__device__ int g_bsum[NBLK];
__device__ int g_bbase[NBLK];
__device__ uint32_t g_perm[NE];     // packed payload: col | (rel<<16)

__device__ __forceinline__ void cp_async16(uint32_t saddr, const void* gaddr) {
    asm volatile("cp.async.cg.shared.global [%0], [%1], 16;" :: "r"(saddr), "l"(gaddr));
}
__device__ __forceinline__ void cp_async16_pred(uint32_t saddr, const void* gaddr, int sz) {
    asm volatile("cp.async.cg.shared.global [%0], [%1], 16, %2;"
                 :: "r"(saddr), "l"(gaddr), "r"(sz));
}
__device__ __forceinline__ uint32_t smem_u32(const void* p) {
    uint32_t a;
    asm("{ .reg .u64 t; cvta.to.shared.u64 t, %1; cvt.u32.u64 %0, t; }" : "=r"(a) : "l"(p));
    return a;
}
__device__ __forceinline__ void ldsm_x4(uint32_t* r, uint32_t addr) {
    asm volatile("ldmatrix.sync.aligned.m8n8.x4.shared.b16 {%0,%1,%2,%3}, [%4];"
                 : "=r"(r[0]), "=r"(r[1]), "=r"(r[2]), "=r"(r[3]) : "r"(addr));
}
__device__ __forceinline__ void ldsm_x4_t(uint32_t* r, uint32_t addr) {
    asm volatile("ldmatrix.sync.aligned.m8n8.x4.trans.shared.b16 {%0,%1,%2,%3}, [%4];"
                 : "=r"(r[0]), "=r"(r[1]), "=r"(r[2]), "=r"(r[3]) : "r"(addr));
}

// ---------------------------------------------------------------------------
// fp32 -> fp16 convert, float4-vectorized
// ---------------------------------------------------------------------------
__global__ void rgcn_tohalf(const float4* __restrict__ src, half2* __restrict__ dst, int n4) {
    int i = blockIdx.x * blockDim.x + threadIdx.x;
    if (i >= n4) return;
    float4 v = src[i];
    dst[2 * i]     = __floats2half2_rn(v.x, v.y);
    dst[2 * i + 1] = __floats2half2_rn(v.z, v.w);
}

// ---------------------------------------------------------------------------
// CSR build: count -> 3-phase parallel scan -> fill perm
// ---------------------------------------------------------------------------
__global__ void rgcn_count(const int* __restrict__ edge_index, int* __restrict__ cnt) {
    int e = blockIdx.x * blockDim.x + threadIdx.x;
    if (e < NE) atomicAdd(&cnt[edge_index[e]], 1);
}

__global__ __launch_bounds__(256)
void rgcn_scanA(const int* __restrict__ cnt, int* __restrict__ offs, int* __restrict__ bsum) {
    __shared__ int s[256];
    const int t = threadIdx.x;
    const int i = blockIdx.x * 256 + t;
    int v = (i < NN) ? cnt[i] : 0;
    s[t] = v;
    __syncthreads();
#pragma unroll
    for (int d = 1; d < 256; d <<= 1) {
        int u = (t >= d) ? s[t - d] : 0;
        __syncthreads();
        s[t] += u;
        __syncthreads();
    }
    if (i < NN) offs[i] = s[t] - v;
    if (t == 255) bsum[blockIdx.x] = s[255];
}

__global__ __launch_bounds__(256)
void rgcn_scanB(const int* __restrict__ bsum, int* __restrict__ bbase) {
    __shared__ int s[256];
    const int t = threadIdx.x;
    int v = (t < NBLK) ? bsum[t] : 0;
    s[t] = v;
    __syncthreads();
#pragma unroll
    for (int d = 1; d < 256; d <<= 1) {
        int u = (t >= d) ? s[t - d] : 0;
        __syncthreads();
        s[t] += u;
        __syncthreads();
    }
    if (t < NBLK) bbase[t] = s[t] - v;
}

__global__ __launch_bounds__(256)
void rgcn_scanC(int* __restrict__ offs, const int* __restrict__ bbase,
                int* __restrict__ curs) {
    const int i = blockIdx.x * 256 + threadIdx.x;
    if (i >= NN) return;
    int o = offs[i] + bbase[blockIdx.x];
    offs[i] = o;
    curs[i] = o;
    if (i == 0) offs[NN] = NE;
}

__global__ void rgcn_fill(const int* __restrict__ edge_index,
                          const int* __restrict__ edge_type,
                          int* __restrict__ curs, uint32_t* __restrict__ perm) {
    int e = blockIdx.x * blockDim.x + threadIdx.x;
    if (e >= NE) return;
    int row = edge_index[e];
    int col = edge_index[NE + e];
    int r   = edge_type[e];
    int pos = atomicAdd(&curs[row], 1);
    perm[pos] = (uint32_t)col | ((uint32_t)r << 16);
}

// ---------------------------------------------------------------------------
// GEMM: xt[r] = x @ W[r], fp16 in/out, fp32 accum. mma m16n8k16.
// CTA: 128 threads (4 warps, 2x2), tile 128x128, warp tile 64x64.
// BK=64, 3-stage cp.async pipeline, ldmatrix fragment loads, 2 CTAs/SM.
// ---------------------------------------------------------------------------
#define BK 64
#define NCH (DI / BK)                 // 4
#define NSTAGE 3
#define APH 72
#define BPH 136
#define A_BYTES (128 * APH * 2)
#define B_BYTES (BK * BPH * 2)
#define STAGE_BYTES (A_BYTES + B_BYTES)
#define SMEM_DYN (NSTAGE * STAGE_BYTES)

__global__ __launch_bounds__(128, 2)
void rgcn_gemm(const __half* __restrict__ x, const __half* __restrict__ w,
               __half* __restrict__ xt) {
    extern __shared__ char smem[];

    const int r  = blockIdx.z;
    const int m0 = blockIdx.x * 128;
    const int n0 = blockIdx.y * 128;

    const int tid  = threadIdx.x;
    const int lane = tid & 31;
    const int wid  = tid >> 5;
    const int wm   = wid & 1;
    const int wn   = wid >> 1;
    const int g    = lane >> 2;
    const int t    = lane & 3;

    const uint32_t sbase = smem_u32(smem);
    const __half* wr = w + (size_t)r * DI * DO;

    float c[4][8][4];
#pragma unroll
    for (int mi = 0; mi < 4; mi++)
#pragma unroll
        for (int ni = 0; ni < 8; ni++)
#pragma unroll
            for (int q = 0; q < 4; q++) c[mi][ni][q] = 0.0f;

    auto load_chunk = [&](int ci, int stage) {
        const int kt = ci * BK;
        const uint32_t sA = sbase + stage * STAGE_BYTES;
        const uint32_t sB = sA + A_BYTES;
#pragma unroll
        for (int u = 0; u < 8; u++) {
            int v = tid + u * 128;
            int row = v >> 3, kq = v & 7;
            int gm = m0 + row;
            uint32_t sa = sA + (row * APH + kq * 8) * 2;
            cp_async16_pred(sa, x + (size_t)gm * DI + kt + kq * 8, (gm < NN) ? 16 : 0);
        }
#pragma unroll
        for (int u = 0; u < 8; u++) {
            int v = tid + u * 128;
            int row = v >> 4, c8 = v & 15;
            uint32_t sb = sB + (row * BPH + c8 * 8) * 2;
            cp_async16(sb, wr + (size_t)(kt + row) * DO + n0 + c8 * 8);
        }
        asm volatile("cp.async.commit_group;" ::: "memory");
    };

    load_chunk(0, 0);
    load_chunk(1, 1);

    const int a_row = wm * 64 + (lane & 15);
    const int a_kof = (lane >> 4) * 8;
    const int b_krow = (lane & 7) + ((lane >> 3) & 1) * 8;
    const int b_col  = wn * 64 + (lane >> 4) * 8;

#pragma unroll
    for (int i = 0; i < NCH; i++) {
        if (i + 2 < NCH) load_chunk(i + 2, (i + 2) % NSTAGE);
        if (i + 2 < NCH)      asm volatile("cp.async.wait_group 2;" ::: "memory");
        else if (i + 1 < NCH) asm volatile("cp.async.wait_group 1;" ::: "memory");
        else                  asm volatile("cp.async.wait_group 0;" ::: "memory");
        __syncthreads();

        const uint32_t sA = sbase + (i % NSTAGE) * STAGE_BYTES;
        const uint32_t sB = sA + A_BYTES;

#pragma unroll
        for (int s = 0; s < 4; s++) {
            const int k16 = s * 16;
            uint32_t a[4][4];
#pragma unroll
            for (int mi = 0; mi < 4; mi++)
                ldsm_x4(a[mi], sA + ((a_row + mi * 16) * APH + k16 + a_kof) * 2);
            uint32_t b[4][4];
#pragma unroll
            for (int p = 0; p < 4; p++)
                ldsm_x4_t(b[p], sB + ((k16 + b_krow) * BPH + b_col + p * 16) * 2);
#pragma unroll
            for (int p = 0; p < 4; p++) {
#pragma unroll
                for (int mi = 0; mi < 4; mi++) {
                    asm volatile(
                        "mma.sync.aligned.m16n8k16.row.col.f32.f16.f16.f32 "
                        "{%0,%1,%2,%3}, {%4,%5,%6,%7}, {%8,%9}, {%0,%1,%2,%3};\n"
                        : "+f"(c[mi][2 * p][0]), "+f"(c[mi][2 * p][1]),
                          "+f"(c[mi][2 * p][2]), "+f"(c[mi][2 * p][3])
                        : "r"(a[mi][0]), "r"(a[mi][1]), "r"(a[mi][2]), "r"(a[mi][3]),
                          "r"(b[p][0]), "r"(b[p][1]));
                    asm volatile(
                        "mma.sync.aligned.m16n8k16.row.col.f32.f16.f16.f32 "
                        "{%0,%1,%2,%3}, {%4,%5,%6,%7}, {%8,%9}, {%0,%1,%2,%3};\n"
                        : "+f"(c[mi][2 * p + 1][0]), "+f"(c[mi][2 * p + 1][1]),
                          "+f"(c[mi][2 * p + 1][2]), "+f"(c[mi][2 * p + 1][3])
                        : "r"(a[mi][0]), "r"(a[mi][1]), "r"(a[mi][2]), "r"(a[mi][3]),
                          "r"(b[p][2]), "r"(b[p][3]));
                }
            }
        }
        __syncthreads();
    }

    __half* xtr = xt + (size_t)r * NN * DO;
#pragma unroll
    for (int mi = 0; mi < 4; mi++) {
#pragma unroll
        for (int ni = 0; ni < 8; ni++) {
            int row0 = m0 + wm * 64 + mi * 16 + g;
            int col  = n0 + wn * 64 + ni * 8 + t * 2;
            if (row0 < NN)
                *(half2*)(xtr + (size_t)row0 * DO + col) =
                    __float22half2_rn(make_float2(c[mi][ni][0], c[mi][ni][1]));
            int row1 = row0 + 8;
            if (row1 < NN)
                *(half2*)(xtr + (size_t)row1 * DO + col) =
                    __float22half2_rn(make_float2(c[mi][ni][2], c[mi][ni][3]));
        }
    }
}

// ---------------------------------------------------------------------------
// Aggregate: one warp per destination node, 8-deep front-batched LDG.128
// pipeline, register accumulation, fused bias+relu.
// ---------------------------------------------------------------------------
__device__ __forceinline__ void acc_vec(float* acc, const uint4& v) {
    float2 f;
    f = __half22float2(*(const half2*)&v.x); acc[0] += f.x; acc[1] += f.y;
    f = __half22float2(*(const half2*)&v.y); acc[2] += f.x; acc[3] += f.y;
    f = __half22float2(*(const half2*)&v.z); acc[4] += f.x; acc[5] += f.y;
    f = __half22float2(*(const half2*)&v.w); acc[6] += f.x; acc[7] += f.y;
}
__device__ __forceinline__ const uint4* msg_ptr(const __half* xt, uint32_t p, int lane) {
    return (const uint4*)(xt + (((size_t)(p >> 16)) * NN + (size_t)(p & 0xFFFFu)) * DO) + lane;
}

__global__ __launch_bounds__(256)
void rgcn_aggregate(const __half* __restrict__ xt,
                    const float* __restrict__ bias,
                    const int* __restrict__ offs,
                    const uint32_t* __restrict__ perm,
                    float* __restrict__ out) {
    const int n = blockIdx.x * 8 + (threadIdx.x >> 5);
    if (n >= NN) return;
    const int lane = threadIdx.x & 31;

    const int s = offs[n];
    const int e = offs[n + 1];

    float acc[8];
#pragma unroll
    for (int k = 0; k < 8; k++) acc[k] = 0.0f;

    int j = s;
    for (; j + 7 < e; j += 8) {
        uint32_t p[8];
#pragma unroll
        for (int q = 0; q < 8; q++) p[q] = perm[j + q];
        uint4 v[8];
#pragma unroll
        for (int q = 0; q < 8; q++) v[q] = __ldg(msg_ptr(xt, p[q], lane));
#pragma unroll
        for (int q = 0; q < 8; q++) acc_vec(acc, v[q]);
    }
    if (j + 3 < e) {
        uint32_t p[4];
#pragma unroll
        for (int q = 0; q < 4; q++) p[q] = perm[j + q];
        uint4 v[4];
#pragma unroll
        for (int q = 0; q < 4; q++) v[q] = __ldg(msg_ptr(xt, p[q], lane));
#pragma unroll
        for (int q = 0; q < 4; q++) acc_vec(acc, v[q]);
        j += 4;
    }
    for (; j < e; j++) {
        uint4 v0 = __ldg(msg_ptr(xt, perm[j], lane));
        acc_vec(acc, v0);
    }

    const float4 b0 = *(const float4*)(bias + lane * 8);
    const float4 b1 = *(const float4*)(bias + lane * 8 + 4);
    float4 o0, o1;
    o0.x = fmaxf(acc[0] + b0.x, 0.f); o0.y = fmaxf(acc[1] + b0.y, 0.f);
    o0.z = fmaxf(acc[2] + b0.z, 0.f); o0.w = fmaxf(acc[3] + b0.w, 0.f);
    o1.x = fmaxf(acc[4] + b1.x, 0.f); o1.y = fmaxf(acc[5] + b1.y, 0.f);
    o1.z = fmaxf(acc[6] + b1.z, 0.f); o1.w = fmaxf(acc[7] + b1.w, 0.f);

    float* dst = out + (size_t)n * DO + lane * 8;
    *(float4*)dst = o0;
    *(float4*)(dst + 4) = o1;
}

extern "C" void kernel_launch(void* const* d_in, const int* in_sizes, int n_in,
                              void* d_out, int out_size) {
    const float* x          = (const float*)d_in[0];
    const int*   edge_index = (const int*)d_in[1];
    const int*   edge_type  = (const int*)d_in[2];
    const float* weight     = (const float*)d_in[3];
    const float* bias       = (const float*)d_in[4];
    float* out = (float*)d_out;

    __half *xh, *wh, *xt;
    int *cnt, *offs, *curs, *bsum, *bbase;
    uint32_t* perm;
    cudaGetSymbolAddress((void**)&xh, g_xh);
    cudaGetSymbolAddress((void**)&wh, g_wh);
    cudaGetSymbolAddress((void**)&xt, g_xt);
    cudaGetSymbolAddress((void**)&cnt, g_cnt);
    cudaGetSymbolAddress((void**)&offs, g_offs);
    cudaGetSymbolAddress((void**)&curs, g_curs);
    cudaGetSymbolAddress((void**)&bsum, g_bsum);
    cudaGetSymbolAddress((void**)&bbase, g_bbase);
    cudaGetSymbolAddress((void**)&perm, g_perm);

    cudaFuncSetAttribute(rgcn_gemm, cudaFuncAttributeMaxDynamicSharedMemorySize, SMEM_DYN);

    const int xn4 = NN * DI / 4;
    const int wn4 = NR * DI * DO / 4;
    rgcn_tohalf<<<(xn4 + 255) / 256, 256>>>((const float4*)x, (half2*)xh, xn4);
    rgcn_tohalf<<<(wn4 + 255) / 256, 256>>>((const float4*)weight, (half2*)wh, wn4);

    // CSR build
    cudaMemsetAsync(cnt, 0, NN * sizeof(int));
    rgcn_count<<<(NE + 255) / 256, 256>>>(edge_index, cnt);
    rgcn_scanA<<<NBLK, 256>>>(cnt, offs, bsum);
    rgcn_scanB<<<1, 256>>>(bsum, bbase);
    rgcn_scanC<<<NBLK, 256>>>(offs, bbase, curs);
    rgcn_fill<<<(NE + 255) / 256, 256>>>(edge_index, edge_type, curs, perm);

    dim3 gg((NN + 127) / 128, DO / 128, NR);     // 391 x 2 x 8
    rgcn_gemm<<<gg, 128, SMEM_DYN>>>(xh, wh, xt);

    rgcn_aggregate<<<(NN + 7) / 8, 256>>>(xt, bias, offs, perm, out);
}

// round 10
// speedup vs baseline: 1.0176x; 1.0176x over previous
#include <cuda_runtime.h>
#include <cuda_fp16.h>
#include <cstdint>
#include <cstddef>

#define NN 50000
#define NE 800000
#define DI 256
#define DO 256
#define NR 8

#define NBLK ((NN + 255) / 256)   // 196 scan blocks

// fp16 scratch: xt[r][n][o]  (204.8 MB)
__device__ __half g_xt[(size_t)NR * NN * DO];
// fp16 copies of x and W
__device__ __half g_xh[(size_t)NN * DI];      // 25.6 MB
__device__ __half g_wh[(size_t)NR * DI * DO]; // 1 MB
// CSR-by-destination scaffolding
__device__ int g_cnt[NN];
__device__ int g_offs[NN + 1];
__device__ int g_curs[NN];
__device__ int g_bsum[NBLK];
__device__ int g_bbase[NBLK];
__device__ uint32_t g_perm[NE];     // packed payload: col | (rel<<16)

__device__ __forceinline__ void cp_async16(uint32_t saddr, const void* gaddr) {
    asm volatile("cp.async.cg.shared.global [%0], [%1], 16;" :: "r"(saddr), "l"(gaddr));
}
__device__ __forceinline__ void cp_async16_pred(uint32_t saddr, const void* gaddr, int sz) {
    asm volatile("cp.async.cg.shared.global [%0], [%1], 16, %2;"
                 :: "r"(saddr), "l"(gaddr), "r"(sz));
}
__device__ __forceinline__ uint32_t smem_u32(const void* p) {
    uint32_t a;
    asm("{ .reg .u64 t; cvta.to.shared.u64 t, %1; cvt.u32.u64 %0, t; }" : "=r"(a) : "l"(p));
    return a;
}
__device__ __forceinline__ void ldsm_x4(uint32_t* r, uint32_t addr) {
    asm volatile("ldmatrix.sync.aligned.m8n8.x4.shared.b16 {%0,%1,%2,%3}, [%4];"
                 : "=r"(r[0]), "=r"(r[1]), "=r"(r[2]), "=r"(r[3]) : "r"(addr));
}
__device__ __forceinline__ void ldsm_x4_t(uint32_t* r, uint32_t addr) {
    asm volatile("ldmatrix.sync.aligned.m8n8.x4.trans.shared.b16 {%0,%1,%2,%3}, [%4];"
                 : "=r"(r[0]), "=r"(r[1]), "=r"(r[2]), "=r"(r[3]) : "r"(addr));
}

// ---------------------------------------------------------------------------
// fp32 -> fp16 convert, float4-vectorized
// ---------------------------------------------------------------------------
__global__ void rgcn_tohalf(const float4* __restrict__ src, half2* __restrict__ dst, int n4) {
    int i = blockIdx.x * blockDim.x + threadIdx.x;
    if (i >= n4) return;
    float4 v = src[i];
    dst[2 * i]     = __floats2half2_rn(v.x, v.y);
    dst[2 * i + 1] = __floats2half2_rn(v.z, v.w);
}

// ---------------------------------------------------------------------------
// CSR build: count -> 3-phase parallel scan -> fill perm
// ---------------------------------------------------------------------------
__global__ void rgcn_count(const int* __restrict__ edge_index, int* __restrict__ cnt) {
    int e = blockIdx.x * blockDim.x + threadIdx.x;
    if (e < NE) atomicAdd(&cnt[edge_index[e]], 1);
}

__global__ __launch_bounds__(256)
void rgcn_scanA(const int* __restrict__ cnt, int* __restrict__ offs, int* __restrict__ bsum) {
    __shared__ int s[256];
    const int t = threadIdx.x;
    const int i = blockIdx.x * 256 + t;
    int v = (i < NN) ? cnt[i] : 0;
    s[t] = v;
    __syncthreads();
#pragma unroll
    for (int d = 1; d < 256; d <<= 1) {
        int u = (t >= d) ? s[t - d] : 0;
        __syncthreads();
        s[t] += u;
        __syncthreads();
    }
    if (i < NN) offs[i] = s[t] - v;
    if (t == 255) bsum[blockIdx.x] = s[255];
}

__global__ __launch_bounds__(256)
void rgcn_scanB(const int* __restrict__ bsum, int* __restrict__ bbase) {
    __shared__ int s[256];
    const int t = threadIdx.x;
    int v = (t < NBLK) ? bsum[t] : 0;
    s[t] = v;
    __syncthreads();
#pragma unroll
    for (int d = 1; d < 256; d <<= 1) {
        int u = (t >= d) ? s[t - d] : 0;
        __syncthreads();
        s[t] += u;
        __syncthreads();
    }
    if (t < NBLK) bbase[t] = s[t] - v;
}

__global__ __launch_bounds__(256)
void rgcn_scanC(int* __restrict__ offs, const int* __restrict__ bbase,
                int* __restrict__ curs) {
    const int i = blockIdx.x * 256 + threadIdx.x;
    if (i >= NN) return;
    int o = offs[i] + bbase[blockIdx.x];
    offs[i] = o;
    curs[i] = o;
    if (i == 0) offs[NN] = NE;
}

__global__ void rgcn_fill(const int* __restrict__ edge_index,
                          const int* __restrict__ edge_type,
                          int* __restrict__ curs, uint32_t* __restrict__ perm) {
    int e = blockIdx.x * blockDim.x + threadIdx.x;
    if (e >= NE) return;
    int row = edge_index[e];
    int col = edge_index[NE + e];
    int r   = edge_type[e];
    int pos = atomicAdd(&curs[row], 1);
    perm[pos] = (uint32_t)col | ((uint32_t)r << 16);
}

// ---------------------------------------------------------------------------
// GEMM: xt[r] = x @ W[r], fp16 in/out, fp32 accum. mma m16n8k16.
// CTA: 128 threads (4 warps, 2x2), tile 128x128, warp tile 64x64.
// BK=64, 3-stage cp.async pipeline, ldmatrix fragment loads, 2 CTAs/SM.
// ---------------------------------------------------------------------------
#define BK 64
#define NCH (DI / BK)                 // 4
#define NSTAGE 3
#define APH 72
#define BPH 136
#define A_BYTES (128 * APH * 2)
#define B_BYTES (BK * BPH * 2)
#define STAGE_BYTES (A_BYTES + B_BYTES)
#define SMEM_DYN (NSTAGE * STAGE_BYTES)

__global__ __launch_bounds__(128, 2)
void rgcn_gemm(const __half* __restrict__ x, const __half* __restrict__ w,
               __half* __restrict__ xt) {
    extern __shared__ char smem[];

    const int r  = blockIdx.z;
    const int m0 = blockIdx.x * 128;
    const int n0 = blockIdx.y * 128;

    const int tid  = threadIdx.x;
    const int lane = tid & 31;
    const int wid  = tid >> 5;
    const int wm   = wid & 1;
    const int wn   = wid >> 1;
    const int g    = lane >> 2;
    const int t    = lane & 3;

    const uint32_t sbase = smem_u32(smem);
    const __half* wr = w + (size_t)r * DI * DO;

    float c[4][8][4];
#pragma unroll
    for (int mi = 0; mi < 4; mi++)
#pragma unroll
        for (int ni = 0; ni < 8; ni++)
#pragma unroll
            for (int q = 0; q < 4; q++) c[mi][ni][q] = 0.0f;

    auto load_chunk = [&](int ci, int stage) {
        const int kt = ci * BK;
        const uint32_t sA = sbase + stage * STAGE_BYTES;
        const uint32_t sB = sA + A_BYTES;
#pragma unroll
        for (int u = 0; u < 8; u++) {
            int v = tid + u * 128;
            int row = v >> 3, kq = v & 7;
            int gm = m0 + row;
            uint32_t sa = sA + (row * APH + kq * 8) * 2;
            cp_async16_pred(sa, x + (size_t)gm * DI + kt + kq * 8, (gm < NN) ? 16 : 0);
        }
#pragma unroll
        for (int u = 0; u < 8; u++) {
            int v = tid + u * 128;
            int row = v >> 4, c8 = v & 15;
            uint32_t sb = sB + (row * BPH + c8 * 8) * 2;
            cp_async16(sb, wr + (size_t)(kt + row) * DO + n0 + c8 * 8);
        }
        asm volatile("cp.async.commit_group;" ::: "memory");
    };

    load_chunk(0, 0);
    load_chunk(1, 1);

    const int a_row = wm * 64 + (lane & 15);
    const int a_kof = (lane >> 4) * 8;
    const int b_krow = (lane & 7) + ((lane >> 3) & 1) * 8;
    const int b_col  = wn * 64 + (lane >> 4) * 8;

#pragma unroll
    for (int i = 0; i < NCH; i++) {
        if (i + 2 < NCH) load_chunk(i + 2, (i + 2) % NSTAGE);
        if (i + 2 < NCH)      asm volatile("cp.async.wait_group 2;" ::: "memory");
        else if (i + 1 < NCH) asm volatile("cp.async.wait_group 1;" ::: "memory");
        else                  asm volatile("cp.async.wait_group 0;" ::: "memory");
        __syncthreads();

        const uint32_t sA = sbase + (i % NSTAGE) * STAGE_BYTES;
        const uint32_t sB = sA + A_BYTES;

#pragma unroll
        for (int s = 0; s < 4; s++) {
            const int k16 = s * 16;
            uint32_t a[4][4];
#pragma unroll
            for (int mi = 0; mi < 4; mi++)
                ldsm_x4(a[mi], sA + ((a_row + mi * 16) * APH + k16 + a_kof) * 2);
            uint32_t b[4][4];
#pragma unroll
            for (int p = 0; p < 4; p++)
                ldsm_x4_t(b[p], sB + ((k16 + b_krow) * BPH + b_col + p * 16) * 2);
#pragma unroll
            for (int p = 0; p < 4; p++) {
#pragma unroll
                for (int mi = 0; mi < 4; mi++) {
                    asm volatile(
                        "mma.sync.aligned.m16n8k16.row.col.f32.f16.f16.f32 "
                        "{%0,%1,%2,%3}, {%4,%5,%6,%7}, {%8,%9}, {%0,%1,%2,%3};\n"
                        : "+f"(c[mi][2 * p][0]), "+f"(c[mi][2 * p][1]),
                          "+f"(c[mi][2 * p][2]), "+f"(c[mi][2 * p][3])
                        : "r"(a[mi][0]), "r"(a[mi][1]), "r"(a[mi][2]), "r"(a[mi][3]),
                          "r"(b[p][0]), "r"(b[p][1]));
                    asm volatile(
                        "mma.sync.aligned.m16n8k16.row.col.f32.f16.f16.f32 "
                        "{%0,%1,%2,%3}, {%4,%5,%6,%7}, {%8,%9}, {%0,%1,%2,%3};\n"
                        : "+f"(c[mi][2 * p + 1][0]), "+f"(c[mi][2 * p + 1][1]),
                          "+f"(c[mi][2 * p + 1][2]), "+f"(c[mi][2 * p + 1][3])
                        : "r"(a[mi][0]), "r"(a[mi][1]), "r"(a[mi][2]), "r"(a[mi][3]),
                          "r"(b[p][2]), "r"(b[p][3]));
                }
            }
        }
        __syncthreads();
    }

    __half* xtr = xt + (size_t)r * NN * DO;
#pragma unroll
    for (int mi = 0; mi < 4; mi++) {
#pragma unroll
        for (int ni = 0; ni < 8; ni++) {
            int row0 = m0 + wm * 64 + mi * 16 + g;
            int col  = n0 + wn * 64 + ni * 8 + t * 2;
            if (row0 < NN)
                *(half2*)(xtr + (size_t)row0 * DO + col) =
                    __float22half2_rn(make_float2(c[mi][ni][0], c[mi][ni][1]));
            int row1 = row0 + 8;
            if (row1 < NN)
                *(half2*)(xtr + (size_t)row1 * DO + col) =
                    __float22half2_rn(make_float2(c[mi][ni][2], c[mi][ni][3]));
        }
    }
}

// ---------------------------------------------------------------------------
// Aggregate: one warp per destination node, 4-deep LDG.128 pipeline,
// register accumulation, fused bias+relu.
// ---------------------------------------------------------------------------
__device__ __forceinline__ void acc_vec(float* acc, const uint4& v) {
    float2 f;
    f = __half22float2(*(const half2*)&v.x); acc[0] += f.x; acc[1] += f.y;
    f = __half22float2(*(const half2*)&v.y); acc[2] += f.x; acc[3] += f.y;
    f = __half22float2(*(const half2*)&v.z); acc[4] += f.x; acc[5] += f.y;
    f = __half22float2(*(const half2*)&v.w); acc[6] += f.x; acc[7] += f.y;
}
__device__ __forceinline__ const uint4* msg_ptr(const __half* xt, uint32_t p, int lane) {
    return (const uint4*)(xt + (((size_t)(p >> 16)) * NN + (size_t)(p & 0xFFFFu)) * DO) + lane;
}

__global__ __launch_bounds__(256)
void rgcn_aggregate(const __half* __restrict__ xt,
                    const float* __restrict__ bias,
                    const int* __restrict__ offs,
                    const uint32_t* __restrict__ perm,
                    float* __restrict__ out) {
    const int n = blockIdx.x * 8 + (threadIdx.x >> 5);
    if (n >= NN) return;
    const int lane = threadIdx.x & 31;

    const int s = offs[n];
    const int e = offs[n + 1];

    float acc[8];
#pragma unroll
    for (int k = 0; k < 8; k++) acc[k] = 0.0f;

    int j = s;
    for (; j + 3 < e; j += 4) {
        uint32_t p0 = perm[j], p1 = perm[j + 1], p2 = perm[j + 2], p3 = perm[j + 3];
        uint4 v0 = __ldg(msg_ptr(xt, p0, lane));
        uint4 v1 = __ldg(msg_ptr(xt, p1, lane));
        uint4 v2 = __ldg(msg_ptr(xt, p2, lane));
        uint4 v3 = __ldg(msg_ptr(xt, p3, lane));
        acc_vec(acc, v0); acc_vec(acc, v1); acc_vec(acc, v2); acc_vec(acc, v3);
    }
    for (; j < e; j++) {
        uint4 v0 = __ldg(msg_ptr(xt, perm[j], lane));
        acc_vec(acc, v0);
    }

    const float4 b0 = *(const float4*)(bias + lane * 8);
    const float4 b1 = *(const float4*)(bias + lane * 8 + 4);
    float4 o0, o1;
    o0.x = fmaxf(acc[0] + b0.x, 0.f); o0.y = fmaxf(acc[1] + b0.y, 0.f);
    o0.z = fmaxf(acc[2] + b0.z, 0.f); o0.w = fmaxf(acc[3] + b0.w, 0.f);
    o1.x = fmaxf(acc[4] + b1.x, 0.f); o1.y = fmaxf(acc[5] + b1.y, 0.f);
    o1.z = fmaxf(acc[6] + b1.z, 0.f); o1.w = fmaxf(acc[7] + b1.w, 0.f);

    float* dst = out + (size_t)n * DO + lane * 8;
    *(float4*)dst = o0;
    *(float4*)(dst + 4) = o1;
}

extern "C" void kernel_launch(void* const* d_in, const int* in_sizes, int n_in,
                              void* d_out, int out_size) {
    const float* x          = (const float*)d_in[0];
    const int*   edge_index = (const int*)d_in[1];
    const int*   edge_type  = (const int*)d_in[2];
    const float* weight     = (const float*)d_in[3];
    const float* bias       = (const float*)d_in[4];
    float* out = (float*)d_out;

    __half *xh, *wh, *xt;
    int *cnt, *offs, *curs, *bsum, *bbase;
    uint32_t* perm;
    cudaGetSymbolAddress((void**)&xh, g_xh);
    cudaGetSymbolAddress((void**)&wh, g_wh);
    cudaGetSymbolAddress((void**)&xt, g_xt);
    cudaGetSymbolAddress((void**)&cnt, g_cnt);
    cudaGetSymbolAddress((void**)&offs, g_offs);
    cudaGetSymbolAddress((void**)&curs, g_curs);
    cudaGetSymbolAddress((void**)&bsum, g_bsum);
    cudaGetSymbolAddress((void**)&bbase, g_bbase);
    cudaGetSymbolAddress((void**)&perm, g_perm);

    cudaFuncSetAttribute(rgcn_gemm, cudaFuncAttributeMaxDynamicSharedMemorySize, SMEM_DYN);

    // Fork a second stream for the CSR branch (multi-stream graph capture via
    // fork/join events). Created per call; never destroyed mid-capture.
    cudaStream_t s2;
    cudaEvent_t evFork, evJoin;
    cudaStreamCreateWithFlags(&s2, cudaStreamNonBlocking);
    cudaEventCreateWithFlags(&evFork, cudaEventDisableTiming);
    cudaEventCreateWithFlags(&evJoin, cudaEventDisableTiming);

    cudaEventRecord(evFork, 0);
    cudaStreamWaitEvent(s2, evFork, 0);

    // ---- Branch A (stream 0): convert + GEMM ----
    const int xn4 = NN * DI / 4;
    const int wn4 = NR * DI * DO / 4;
    rgcn_tohalf<<<(xn4 + 255) / 256, 256>>>((const float4*)x, (half2*)xh, xn4);
    rgcn_tohalf<<<(wn4 + 255) / 256, 256>>>((const float4*)weight, (half2*)wh, wn4);
    dim3 gg((NN + 127) / 128, DO / 128, NR);     // 391 x 2 x 8
    rgcn_gemm<<<gg, 128, SMEM_DYN>>>(xh, wh, xt);

    // ---- Branch B (stream s2): CSR build ----
    cudaMemsetAsync(cnt, 0, NN * sizeof(int), s2);
    rgcn_count<<<(NE + 255) / 256, 256, 0, s2>>>(edge_index, cnt);
    rgcn_scanA<<<NBLK, 256, 0, s2>>>(cnt, offs, bsum);
    rgcn_scanB<<<1, 256, 0, s2>>>(bsum, bbase);
    rgcn_scanC<<<NBLK, 256, 0, s2>>>(offs, bbase, curs);
    rgcn_fill<<<(NE + 255) / 256, 256, 0, s2>>>(edge_index, edge_type, curs, perm);

    // ---- Join ----
    cudaEventRecord(evJoin, s2);
    cudaStreamWaitEvent(0, evJoin, 0);

    rgcn_aggregate<<<(NN + 7) / 8, 256>>>(xt, bias, offs, perm, out);
}

// round 11
// speedup vs baseline: 1.0279x; 1.0101x over previous
#include <cuda_runtime.h>
#include <cuda_fp16.h>
#include <cstdint>
#include <cstddef>

#define NN 50000
#define NE 800000
#define DI 256
#define DO 256
#define NR 8

#define NB (NN * NR)                  // 400000 (row,rel) buckets
#define SB1 512
#define NBLK2 ((NB + SB1 - 1) / SB1)  // 782 scan blocks

// s[row][rel][di] fp16 aggregate buffer (204.8 MB)
__device__ __half g_s[(size_t)NN * NR * DI];
// fp16 copies of x and W
__device__ __half g_xh[(size_t)NN * DI];      // 25.6 MB (L2-resident)
__device__ __half g_wh[(size_t)NR * DI * DO]; // 1 MB
// CSR-by-(row,rel) scaffolding
__device__ int g_cnt[NB];
__device__ int g_offs[NB + 1];
__device__ int g_curs[NB];
__device__ int g_bsum[NBLK2];
__device__ int g_bbase[NBLK2];
__device__ int g_perm[NE];            // col per slot

__device__ __forceinline__ void cp_async16(uint32_t saddr, const void* gaddr) {
    asm volatile("cp.async.cg.shared.global [%0], [%1], 16;" :: "r"(saddr), "l"(gaddr));
}
__device__ __forceinline__ void cp_async16_pred(uint32_t saddr, const void* gaddr, int sz) {
    asm volatile("cp.async.cg.shared.global [%0], [%1], 16, %2;"
                 :: "r"(saddr), "l"(gaddr), "r"(sz));
}
__device__ __forceinline__ uint32_t smem_u32(const void* p) {
    uint32_t a;
    asm("{ .reg .u64 t; cvta.to.shared.u64 t, %1; cvt.u32.u64 %0, t; }" : "=r"(a) : "l"(p));
    return a;
}
__device__ __forceinline__ void ldsm_x4(uint32_t* r, uint32_t addr) {
    asm volatile("ldmatrix.sync.aligned.m8n8.x4.shared.b16 {%0,%1,%2,%3}, [%4];"
                 : "=r"(r[0]), "=r"(r[1]), "=r"(r[2]), "=r"(r[3]) : "r"(addr));
}
__device__ __forceinline__ void ldsm_x4_t(uint32_t* r, uint32_t addr) {
    asm volatile("ldmatrix.sync.aligned.m8n8.x4.trans.shared.b16 {%0,%1,%2,%3}, [%4];"
                 : "=r"(r[0]), "=r"(r[1]), "=r"(r[2]), "=r"(r[3]) : "r"(addr));
}

// ---------------------------------------------------------------------------
// fp32 -> fp16 convert
// ---------------------------------------------------------------------------
__global__ void rgcn_tohalf(const float4* __restrict__ src, half2* __restrict__ dst, int n4) {
    int i = blockIdx.x * blockDim.x + threadIdx.x;
    if (i >= n4) return;
    float4 v = src[i];
    dst[2 * i]     = __floats2half2_rn(v.x, v.y);
    dst[2 * i + 1] = __floats2half2_rn(v.z, v.w);
}

// ---------------------------------------------------------------------------
// CSR by (row,rel): count -> 3-phase scan -> fill
// ---------------------------------------------------------------------------
__global__ void rgcn_count(const int* __restrict__ edge_index,
                           const int* __restrict__ edge_type, int* __restrict__ cnt) {
    int e = blockIdx.x * blockDim.x + threadIdx.x;
    if (e < NE) atomicAdd(&cnt[edge_index[e] * NR + edge_type[e]], 1);
}

__global__ __launch_bounds__(SB1)
void rgcn_scanA(const int* __restrict__ cnt, int* __restrict__ offs, int* __restrict__ bsum) {
    __shared__ int s[SB1];
    const int t = threadIdx.x;
    const int i = blockIdx.x * SB1 + t;
    int v = (i < NB) ? cnt[i] : 0;
    s[t] = v;
    __syncthreads();
#pragma unroll
    for (int d = 1; d < SB1; d <<= 1) {
        int u = (t >= d) ? s[t - d] : 0;
        __syncthreads();
        s[t] += u;
        __syncthreads();
    }
    if (i < NB) offs[i] = s[t] - v;
    if (t == SB1 - 1) bsum[blockIdx.x] = s[SB1 - 1];
}

__global__ __launch_bounds__(1024)
void rgcn_scanB(const int* __restrict__ bsum, int* __restrict__ bbase) {
    __shared__ int s[1024];
    const int t = threadIdx.x;
    int v = (t < NBLK2) ? bsum[t] : 0;
    s[t] = v;
    __syncthreads();
#pragma unroll
    for (int d = 1; d < 1024; d <<= 1) {
        int u = (t >= d) ? s[t - d] : 0;
        __syncthreads();
        s[t] += u;
        __syncthreads();
    }
    if (t < NBLK2) bbase[t] = s[t] - v;
}

__global__ __launch_bounds__(SB1)
void rgcn_scanC(int* __restrict__ offs, const int* __restrict__ bbase,
                int* __restrict__ curs) {
    const int i = blockIdx.x * SB1 + threadIdx.x;
    if (i >= NB) return;
    int o = offs[i] + bbase[blockIdx.x];
    offs[i] = o;
    curs[i] = o;
    if (i == 0) offs[NB] = NE;
}

__global__ void rgcn_fill(const int* __restrict__ edge_index,
                          const int* __restrict__ edge_type,
                          int* __restrict__ curs, int* __restrict__ perm) {
    int e = blockIdx.x * blockDim.x + threadIdx.x;
    if (e >= NE) return;
    int pos = atomicAdd(&curs[edge_index[e] * NR + edge_type[e]], 1);
    perm[pos] = edge_index[NE + e];
}

// ---------------------------------------------------------------------------
// Build s: one warp per row. Gather x[col] (L2-resident) per relation,
// fp32 accumulate, store fp16 s[row][rel][:].
// ---------------------------------------------------------------------------
__global__ __launch_bounds__(256)
void rgcn_build_s(const __half* __restrict__ xh,
                  const int* __restrict__ offs,
                  const int* __restrict__ perm,
                  __half* __restrict__ s) {
    const int row = blockIdx.x * 8 + (threadIdx.x >> 5);
    if (row >= NN) return;
    const int lane = threadIdx.x & 31;

    __half* srow = s + (size_t)row * NR * DI + lane * 8;

#pragma unroll
    for (int r = 0; r < NR; r++) {
        const int b = row * NR + r;
        int j = offs[b];
        const int je = offs[b + 1];
        float acc[8];
#pragma unroll
        for (int k = 0; k < 8; k++) acc[k] = 0.0f;

        for (; j + 1 < je; j += 2) {
            int c0 = perm[j], c1 = perm[j + 1];
            uint4 v0 = __ldg((const uint4*)(xh + (size_t)c0 * DI) + lane);
            uint4 v1 = __ldg((const uint4*)(xh + (size_t)c1 * DI) + lane);
            float2 f;
            f = __half22float2(*(const half2*)&v0.x); acc[0] += f.x; acc[1] += f.y;
            f = __half22float2(*(const half2*)&v0.y); acc[2] += f.x; acc[3] += f.y;
            f = __half22float2(*(const half2*)&v0.z); acc[4] += f.x; acc[5] += f.y;
            f = __half22float2(*(const half2*)&v0.w); acc[6] += f.x; acc[7] += f.y;
            f = __half22float2(*(const half2*)&v1.x); acc[0] += f.x; acc[1] += f.y;
            f = __half22float2(*(const half2*)&v1.y); acc[2] += f.x; acc[3] += f.y;
            f = __half22float2(*(const half2*)&v1.z); acc[4] += f.x; acc[5] += f.y;
            f = __half22float2(*(const half2*)&v1.w); acc[6] += f.x; acc[7] += f.y;
        }
        if (j < je) {
            int c0 = perm[j];
            uint4 v0 = __ldg((const uint4*)(xh + (size_t)c0 * DI) + lane);
            float2 f;
            f = __half22float2(*(const half2*)&v0.x); acc[0] += f.x; acc[1] += f.y;
            f = __half22float2(*(const half2*)&v0.y); acc[2] += f.x; acc[3] += f.y;
            f = __half22float2(*(const half2*)&v0.z); acc[4] += f.x; acc[5] += f.y;
            f = __half22float2(*(const half2*)&v0.w); acc[6] += f.x; acc[7] += f.y;
        }

        uint4 o;
        *(half2*)&o.x = __floats2half2_rn(acc[0], acc[1]);
        *(half2*)&o.y = __floats2half2_rn(acc[2], acc[3]);
        *(half2*)&o.z = __floats2half2_rn(acc[4], acc[5]);
        *(half2*)&o.w = __floats2half2_rn(acc[6], acc[7]);
        *(uint4*)(srow + r * DI) = o;
    }
}

// ---------------------------------------------------------------------------
// GEMM2: out[m] = relu( sum_r s[m][r] @ W[r] + bias ), fp32 out.
// Tile 128x128, warp 64x64, 32 pipeline steps (8 rel x 4 K-chunks),
// persistent accumulators across relations, 3-stage cp.async, 2 CTAs/SM.
// ---------------------------------------------------------------------------
#define BK 64
#define NSTEP (NR * (DI / BK))        // 32
#define NSTAGE 3
#define APH 72
#define BPH 136
#define A_BYTES (128 * APH * 2)
#define B_BYTES (BK * BPH * 2)
#define STAGE_BYTES (A_BYTES + B_BYTES)
#define SMEM_DYN (NSTAGE * STAGE_BYTES)

__global__ __launch_bounds__(128, 2)
void rgcn_gemm2(const __half* __restrict__ s, const __half* __restrict__ w,
                const float* __restrict__ bias, float* __restrict__ out) {
    extern __shared__ char smem[];

    const int m0 = blockIdx.x * 128;
    const int n0 = blockIdx.y * 128;

    const int tid  = threadIdx.x;
    const int lane = tid & 31;
    const int wid  = tid >> 5;
    const int wm   = wid & 1;
    const int wn   = wid >> 1;
    const int g    = lane >> 2;
    const int t    = lane & 3;

    const uint32_t sbase = smem_u32(smem);

    float c[4][8][4];
#pragma unroll
    for (int mi = 0; mi < 4; mi++)
#pragma unroll
        for (int ni = 0; ni < 8; ni++)
#pragma unroll
            for (int q = 0; q < 4; q++) c[mi][ni][q] = 0.0f;

    auto load_chunk = [&](int step, int stage) {
        const int r  = step >> 2;
        const int kt = (step & 3) * BK;
        const uint32_t sA = sbase + stage * STAGE_BYTES;
        const uint32_t sB = sA + A_BYTES;
#pragma unroll
        for (int u = 0; u < 8; u++) {
            int v = tid + u * 128;
            int row = v >> 3, kq = v & 7;
            int gm = m0 + row;
            uint32_t sa = sA + (row * APH + kq * 8) * 2;
            const __half* gp = s + ((size_t)gm * NR + r) * DI + kt + kq * 8;
            cp_async16_pred(sa, gp, (gm < NN) ? 16 : 0);
        }
#pragma unroll
        for (int u = 0; u < 8; u++) {
            int v = tid + u * 128;
            int row = v >> 4, c8 = v & 15;
            uint32_t sb = sB + (row * BPH + c8 * 8) * 2;
            cp_async16(sb, w + (size_t)r * DI * DO + (size_t)(kt + row) * DO + n0 + c8 * 8);
        }
        asm volatile("cp.async.commit_group;" ::: "memory");
    };

    load_chunk(0, 0);
    load_chunk(1, 1);

    const int a_row = wm * 64 + (lane & 15);
    const int a_kof = (lane >> 4) * 8;
    const int b_krow = (lane & 7) + ((lane >> 3) & 1) * 8;
    const int b_col  = wn * 64 + (lane >> 4) * 8;

    for (int i = 0; i < NSTEP; i++) {
        if (i + 2 < NSTEP) load_chunk(i + 2, (i + 2) % NSTAGE);
        if (i + 2 < NSTEP)      asm volatile("cp.async.wait_group 2;" ::: "memory");
        else if (i + 1 < NSTEP) asm volatile("cp.async.wait_group 1;" ::: "memory");
        else                    asm volatile("cp.async.wait_group 0;" ::: "memory");
        __syncthreads();

        const uint32_t sA = sbase + (i % NSTAGE) * STAGE_BYTES;
        const uint32_t sB = sA + A_BYTES;

#pragma unroll
        for (int ks = 0; ks < 4; ks++) {
            const int k16 = ks * 16;
            uint32_t a[4][4];
#pragma unroll
            for (int mi = 0; mi < 4; mi++)
                ldsm_x4(a[mi], sA + ((a_row + mi * 16) * APH + k16 + a_kof) * 2);
            uint32_t b[4][4];
#pragma unroll
            for (int p = 0; p < 4; p++)
                ldsm_x4_t(b[p], sB + ((k16 + b_krow) * BPH + b_col + p * 16) * 2);
#pragma unroll
            for (int p = 0; p < 4; p++) {
#pragma unroll
                for (int mi = 0; mi < 4; mi++) {
                    asm volatile(
                        "mma.sync.aligned.m16n8k16.row.col.f32.f16.f16.f32 "
                        "{%0,%1,%2,%3}, {%4,%5,%6,%7}, {%8,%9}, {%0,%1,%2,%3};\n"
                        : "+f"(c[mi][2 * p][0]), "+f"(c[mi][2 * p][1]),
                          "+f"(c[mi][2 * p][2]), "+f"(c[mi][2 * p][3])
                        : "r"(a[mi][0]), "r"(a[mi][1]), "r"(a[mi][2]), "r"(a[mi][3]),
                          "r"(b[p][0]), "r"(b[p][1]));
                    asm volatile(
                        "mma.sync.aligned.m16n8k16.row.col.f32.f16.f16.f32 "
                        "{%0,%1,%2,%3}, {%4,%5,%6,%7}, {%8,%9}, {%0,%1,%2,%3};\n"
                        : "+f"(c[mi][2 * p + 1][0]), "+f"(c[mi][2 * p + 1][1]),
                          "+f"(c[mi][2 * p + 1][2]), "+f"(c[mi][2 * p + 1][3])
                        : "r"(a[mi][0]), "r"(a[mi][1]), "r"(a[mi][2]), "r"(a[mi][3]),
                          "r"(b[p][2]), "r"(b[p][3]));
                }
            }
        }
        __syncthreads();
    }

    // epilogue: bias + relu -> fp32 out
    float2 bv[8];
#pragma unroll
    for (int ni = 0; ni < 8; ni++)
        bv[ni] = *(const float2*)(bias + n0 + wn * 64 + ni * 8 + t * 2);

#pragma unroll
    for (int mi = 0; mi < 4; mi++) {
#pragma unroll
        for (int ni = 0; ni < 8; ni++) {
            int row0 = m0 + wm * 64 + mi * 16 + g;
            int col  = n0 + wn * 64 + ni * 8 + t * 2;
            if (row0 < NN) {
                float2 o;
                o.x = fmaxf(c[mi][ni][0] + bv[ni].x, 0.f);
                o.y = fmaxf(c[mi][ni][1] + bv[ni].y, 0.f);
                *(float2*)(out + (size_t)row0 * DO + col) = o;
            }
            int row1 = row0 + 8;
            if (row1 < NN) {
                float2 o;
                o.x = fmaxf(c[mi][ni][2] + bv[ni].x, 0.f);
                o.y = fmaxf(c[mi][ni][3] + bv[ni].y, 0.f);
                *(float2*)(out + (size_t)row1 * DO + col) = o;
            }
        }
    }
}

extern "C" void kernel_launch(void* const* d_in, const int* in_sizes, int n_in,
                              void* d_out, int out_size) {
    const float* x          = (const float*)d_in[0];
    const int*   edge_index = (const int*)d_in[1];
    const int*   edge_type  = (const int*)d_in[2];
    const float* weight     = (const float*)d_in[3];
    const float* bias       = (const float*)d_in[4];
    float* out = (float*)d_out;

    __half *xh, *wh, *sbuf;
    int *cnt, *offs, *curs, *bsum, *bbase, *perm;
    cudaGetSymbolAddress((void**)&xh, g_xh);
    cudaGetSymbolAddress((void**)&wh, g_wh);
    cudaGetSymbolAddress((void**)&sbuf, g_s);
    cudaGetSymbolAddress((void**)&cnt, g_cnt);
    cudaGetSymbolAddress((void**)&offs, g_offs);
    cudaGetSymbolAddress((void**)&curs, g_curs);
    cudaGetSymbolAddress((void**)&bsum, g_bsum);
    cudaGetSymbolAddress((void**)&bbase, g_bbase);
    cudaGetSymbolAddress((void**)&perm, g_perm);

    cudaFuncSetAttribute(rgcn_gemm2, cudaFuncAttributeMaxDynamicSharedMemorySize, SMEM_DYN);

    // Fork: CSR build on s2, conversions on stream 0.
    cudaStream_t s2;
    cudaEvent_t evFork, evJoin;
    cudaStreamCreateWithFlags(&s2, cudaStreamNonBlocking);
    cudaEventCreateWithFlags(&evFork, cudaEventDisableTiming);
    cudaEventCreateWithFlags(&evJoin, cudaEventDisableTiming);

    cudaEventRecord(evFork, 0);
    cudaStreamWaitEvent(s2, evFork, 0);

    // Branch A: conversions
    const int xn4 = NN * DI / 4;
    const int wn4 = NR * DI * DO / 4;
    rgcn_tohalf<<<(xn4 + 255) / 256, 256>>>((const float4*)x, (half2*)xh, xn4);
    rgcn_tohalf<<<(wn4 + 255) / 256, 256>>>((const float4*)weight, (half2*)wh, wn4);

    // Branch B: CSR by (row,rel)
    cudaMemsetAsync(cnt, 0, NB * sizeof(int), s2);
    rgcn_count<<<(NE + 255) / 256, 256, 0, s2>>>(edge_index, edge_type, cnt);
    rgcn_scanA<<<NBLK2, SB1, 0, s2>>>(cnt, offs, bsum);
    rgcn_scanB<<<1, 1024, 0, s2>>>(bsum, bbase);
    rgcn_scanC<<<NBLK2, SB1, 0, s2>>>(offs, bbase, curs);
    rgcn_fill<<<(NE + 255) / 256, 256, 0, s2>>>(edge_index, edge_type, curs, perm);

    cudaEventRecord(evJoin, s2);
    cudaStreamWaitEvent(0, evJoin, 0);

    // Aggregate-first: build s, then fused GEMM+bias+relu
    rgcn_build_s<<<(NN + 7) / 8, 256>>>(xh, offs, perm, sbuf);

    dim3 gg((NN + 127) / 128, DO / 128);         // 391 x 2
    rgcn_gemm2<<<gg, 128, SMEM_DYN>>>(sbuf, wh, bias, out);
}